// round 2
// baseline (speedup 1.0000x reference)
#include <cuda_runtime.h>
#include <math_constants.h>

#define NCLS    1000
#define NPAD    1024
#define KTOP    5
#define BMAX    64
#define THREADS 512

__device__ float g_row_loss[BMAX];

__global__ __launch_bounds__(THREADS)
void topk_row_kernel(const float* __restrict__ outp,
                     const int*   __restrict__ target)
{
    __shared__ float sval[NPAD];     // sorted values (descending)
    __shared__ int   sidx[NPAD];     // original indices
    __shared__ float scan_a[NPAD];   // scan ping
    __shared__ float scan_b[NPAD];   // scan pong
    __shared__ float rcp[NCLS + 1];  // 1/len table
    __shared__ int   s_p;
    __shared__ float s_sp;
    __shared__ float red[THREADS / 32];

    const int b   = blockIdx.x;
    const int tid = threadIdx.x;
    const float* row = outp + (size_t)b * NCLS;
    const int tgt = target[b];

    // Load row, pad with -inf
    for (int i = tid; i < NPAD; i += THREADS) {
        sval[i] = (i < NCLS) ? row[i] : -CUDART_INF_F;
        sidx[i] = i;
    }
    for (int i = tid; i <= NCLS; i += THREADS)
        rcp[i] = (i > 0) ? (1.0f / (float)i) : 0.0f;
    __syncthreads();

    // Bitonic sort: descending by value, ascending by index on ties
    // (matches stable argsort of -theta)
    for (int k = 2; k <= NPAD; k <<= 1) {
        for (int j = k >> 1; j > 0; j >>= 1) {
            #pragma unroll
            for (int t = 0; t < NPAD / THREADS; t++) {
                int i = tid + t * THREADS;
                int ixj = i ^ j;
                if (ixj > i) {
                    float v1 = sval[i],  v2 = sval[ixj];
                    int   i1 = sidx[i],  i2 = sidx[ixj];
                    // true if element at i belongs AFTER element at ixj in
                    // the desired (descending) order
                    bool i_after = (v1 < v2) || (v1 == v2 && i1 > i2);
                    bool do_swap = ((i & k) == 0) ? i_after : !i_after;
                    if (do_swap) {
                        sval[i] = v2; sval[ixj] = v1;
                        sidx[i] = i2; sidx[ixj] = i1;
                    }
                }
            }
            __syncthreads();
        }
    }

    // Find p: sorted position of target index (target always finite -> p < NCLS)
    for (int i = tid; i < NCLS; i += THREADS) {
        if (sidx[i] == tgt) { s_p = i; s_sp = sval[i]; }
    }
    __syncthreads();

    // y[i] = s[i] - w[i], w[i] = NCLS - i ; pad zeros
    for (int i = tid; i < NPAD; i += THREADS)
        scan_a[i] = (i < NCLS) ? (sval[i] - (float)(NCLS - i)) : 0.0f;
    __syncthreads();

    // Hillis-Steele inclusive scan over NPAD (10 stages)
    float* src = scan_a;
    float* dst = scan_b;
    for (int off = 1; off < NPAD; off <<= 1) {
        #pragma unroll
        for (int t = 0; t < NPAD / THREADS; t++) {
            int i = tid + t * THREADS;
            dst[i] = (i >= off) ? (src[i] + src[i - off]) : src[i];
        }
        __syncthreads();
        float* tmp = src; src = dst; dst = tmp;
    }
    // src[i] = cs[i+1] (inclusive prefix sum); cs[0] = 0

    const int   p  = s_p;
    const float sp = s_sp;
    const float* cs1 = src;

    // sol_p = min_{j<=p} max_{k>=p} (cs[k+1]-cs[j]) / (k-j+1)
    float gmin = CUDART_INF_F;
    for (int j = tid; j <= p; j += THREADS) {
        const float csj = (j == 0) ? 0.0f : cs1[j - 1];
        float gmax = -CUDART_INF_F;
        for (int k = p; k < NCLS; k++) {
            float m = (cs1[k] - csj) * rcp[k - j + 1];
            gmax = fmaxf(gmax, m);
        }
        gmin = fminf(gmin, gmax);
    }

    // Block min-reduce
    #pragma unroll
    for (int o = 16; o; o >>= 1)
        gmin = fminf(gmin, __shfl_xor_sync(0xFFFFFFFFu, gmin, o));
    if ((tid & 31) == 0) red[tid >> 5] = gmin;
    __syncthreads();
    if (tid < 32) {
        float v = (tid < THREADS / 32) ? red[tid] : CUDART_INF_F;
        #pragma unroll
        for (int o = 8; o; o >>= 1)
            v = fminf(v, __shfl_xor_sync(0xFFFFFFFFu, v, o));
        if (tid == 0) {
            float rank = sp - v;                       // ranks_label
            float loss = (float)(NCLS - KTOP + 1) - rank;  // 996 - rank
            g_row_loss[b] = fmaxf(0.0f, loss);
        }
    }
}

__global__ void topk_reduce_kernel(float* __restrict__ out, int Bn)
{
    __shared__ float s[2];
    int tid = threadIdx.x;
    float v = (tid < Bn) ? g_row_loss[tid] : 0.0f;
    #pragma unroll
    for (int o = 16; o; o >>= 1)
        v += __shfl_xor_sync(0xFFFFFFFFu, v, o);
    if ((tid & 31) == 0) s[tid >> 5] = v;
    __syncthreads();
    if (tid == 0) out[0] = (s[0] + s[1]) / (float)Bn;
}

extern "C" void kernel_launch(void* const* d_in, const int* in_sizes, int n_in,
                              void* d_out, int out_size)
{
    const float* outp   = (const float*)d_in[0];
    const int*   target = (const int*)d_in[1];
    float*       out    = (float*)d_out;

    int B = in_sizes[1];          // 64 rows
    if (B > BMAX) B = BMAX;

    topk_row_kernel<<<B, THREADS>>>(outp, target);
    topk_reduce_kernel<<<1, 64>>>(out, B);
}

// round 6
// speedup vs baseline: 1.0011x; 1.0011x over previous
#include <cuda_runtime.h>
#include <math_constants.h>

#define NCLS    1000
#define NPAD    1024
#define KTOP    5
#define BMAX    64
#define THREADS 512
#define NWARP   (THREADS / 32)

__device__ float        g_row_loss[BMAX];
__device__ unsigned int g_done_cnt = 0;

__global__ __launch_bounds__(THREADS)
void topk_fused_kernel(const float* __restrict__ outp,
                       const int*   __restrict__ target,
                       float*       __restrict__ out,
                       int B)
{
    __shared__ float sval[NPAD];     // values (sorted descending in-place)
    __shared__ float scan_a[NPAD];   // scan ping
    __shared__ float scan_b[NPAD];   // scan pong
    __shared__ float rcp[NCLS + 1];  // 1/len table
    __shared__ int   cred[NWARP];    // per-warp p-counts
    __shared__ float red[NWARP];     // min-reduce scratch
    __shared__ int   s_p;
    __shared__ int   s_last;

    const int b   = blockIdx.x;
    const int tid = threadIdx.x;
    const float* row = outp + (size_t)b * NCLS;
    const int   tgt = target[b];
    const float vt  = __ldg(row + tgt);

    // Load row (pad -inf) and count rank position of target:
    //   p = #(v > vt) + #(v == vt && i < tgt)   (stable argsort of -theta)
    int cnt = 0;
    for (int i = tid; i < NPAD; i += THREADS) {
        float v = (i < NCLS) ? row[i] : -CUDART_INF_F;
        sval[i] = v;
        if (i < NCLS) cnt += (v > vt) || (v == vt && i < tgt);
    }
    for (int i = tid; i <= NCLS; i += THREADS)
        rcp[i] = (i > 0) ? (1.0f / (float)i) : 0.0f;

    #pragma unroll
    for (int o = 16; o; o >>= 1)
        cnt += __shfl_xor_sync(0xFFFFFFFFu, cnt, o);
    if ((tid & 31) == 0) cred[tid >> 5] = cnt;
    __syncthreads();
    if (tid == 0) {
        int p = 0;
        #pragma unroll
        for (int w = 0; w < NWARP; w++) p += cred[w];
        s_p = p;
    }

    // Bitonic sort (values only), descending
    for (int k = 2; k <= NPAD; k <<= 1) {
        for (int j = k >> 1; j > 0; j >>= 1) {
            __syncthreads();
            #pragma unroll
            for (int t = 0; t < NPAD / THREADS; t++) {
                int i = tid + t * THREADS;
                int ixj = i ^ j;
                if (ixj > i) {
                    float v1 = sval[i], v2 = sval[ixj];
                    bool i_after = (v1 < v2);
                    bool do_swap = ((i & k) == 0) ? i_after : !i_after;
                    if (do_swap) { sval[i] = v2; sval[ixj] = v1; }
                }
            }
        }
    }
    __syncthreads();

    // y[i] = s[i] - (NCLS - i); pad zeros
    for (int i = tid; i < NPAD; i += THREADS)
        scan_a[i] = (i < NCLS) ? (sval[i] - (float)(NCLS - i)) : 0.0f;
    __syncthreads();

    // Hillis-Steele inclusive scan (10 stages)
    float* src = scan_a;
    float* dst = scan_b;
    for (int off = 1; off < NPAD; off <<= 1) {
        #pragma unroll
        for (int t = 0; t < NPAD / THREADS; t++) {
            int i = tid + t * THREADS;
            dst[i] = (i >= off) ? (src[i] + src[i - off]) : src[i];
        }
        __syncthreads();
        float* tmp = src; src = dst; dst = tmp;
    }
    // src[i] = cs[i+1]; cs[0] = 0

    const int   p  = s_p;
    const float sp = sval[p];
    const float* cs1 = src;

    // sol_p = min_{j<=p} max_{k>=p} (cs[k+1]-cs[j]) * rcp[k-j+1]
    // 4 accumulators to break the FMAX dependency chain.
    float gmin = CUDART_INF_F;
    for (int j = tid; j <= p; j += THREADS) {
        const float csj = (j == 0) ? 0.0f : cs1[j - 1];
        const float* rj = rcp + (1 - j);
        float m0 = -CUDART_INF_F, m1 = -CUDART_INF_F;
        float m2 = -CUDART_INF_F, m3 = -CUDART_INF_F;
        int k = p;
        for (; k + 3 < NCLS; k += 4) {
            m0 = fmaxf(m0, (cs1[k]     - csj) * rj[k]);
            m1 = fmaxf(m1, (cs1[k + 1] - csj) * rj[k + 1]);
            m2 = fmaxf(m2, (cs1[k + 2] - csj) * rj[k + 2]);
            m3 = fmaxf(m3, (cs1[k + 3] - csj) * rj[k + 3]);
        }
        for (; k < NCLS; k++)
            m0 = fmaxf(m0, (cs1[k] - csj) * rj[k]);
        float gmax = fmaxf(fmaxf(m0, m1), fmaxf(m2, m3));
        gmin = fminf(gmin, gmax);
    }

    #pragma unroll
    for (int o = 16; o; o >>= 1)
        gmin = fminf(gmin, __shfl_xor_sync(0xFFFFFFFFu, gmin, o));
    if ((tid & 31) == 0) red[tid >> 5] = gmin;
    __syncthreads();
    if (tid == 0) {
        float v = CUDART_INF_F;
        #pragma unroll
        for (int w = 0; w < NWARP; w++) v = fminf(v, red[w]);
        float rank = sp - v;
        float loss = fmaxf(0.0f, (float)(NCLS - KTOP + 1) - rank);
        g_row_loss[b] = loss;
        __threadfence();
        unsigned t = atomicAdd(&g_done_cnt, 1u);
        s_last = (t == (unsigned)(B - 1));
    }
    __syncthreads();

    // Last CTA to finish reduces all row losses and writes the mean.
    if (s_last) {
        if (tid < 32) {
            __threadfence();
            float v = 0.0f;
            for (int i = tid; i < B; i += 32)
                v += g_row_loss[i];
            #pragma unroll
            for (int o = 16; o; o >>= 1)
                v += __shfl_xor_sync(0xFFFFFFFFu, v, o);
            if (tid == 0) {
                out[0] = v / (float)B;
                g_done_cnt = 0;   // reset for next graph replay
                __threadfence();
            }
        }
    }
}

extern "C" void kernel_launch(void* const* d_in, const int* in_sizes, int n_in,
                              void* d_out, int out_size)
{
    const float* outp   = (const float*)d_in[0];
    const int*   target = (const int*)d_in[1];
    float*       out    = (float*)d_out;

    int B = in_sizes[1];
    if (B > BMAX) B = BMAX;

    topk_fused_kernel<<<B, THREADS>>>(outp, target, out, B);
}